// round 16
// baseline (speedup 1.0000x reference)
#include <cuda_runtime.h>
#include <cuda_bf16.h>
#include <cstdint>

#define D_MODEL 1024
#define N_HEADS 16
#define D_K     64
#define B_      2
#define T_      2048
#define M_ROWS  (B_ * T_)      // 4096
#define ASZ     (M_ROWS * D_MODEL)
#define WSZ     (D_MODEL * D_MODEL)

// ---------------- scratch (static device globals: allowed) ----------------
__device__ __nv_bfloat16 g_Ah[3 * ASZ];
__device__ __nv_bfloat16 g_Al[3 * ASZ];
__device__ __nv_bfloat16 g_Wh[4 * WSZ];
__device__ __nv_bfloat16 g_Wl[4 * WSZ];
__device__ __nv_bfloat16 g_Qh[ASZ];
__device__ __nv_bfloat16 g_Ql[ASZ];
__device__ __nv_bfloat16 g_Kh[ASZ];
__device__ __nv_bfloat16 g_Kl[ASZ];
__device__ __nv_bfloat16 g_Vh[ASZ];
__device__ __nv_bfloat16 g_Vl[ASZ];
__device__ __nv_bfloat16 g_Anh[ASZ];
__device__ __nv_bfloat16 g_Anl[ASZ];

// =====================================================================
// portable tensor-core helpers (valid on plain sm_103 target)
// =====================================================================
__device__ __forceinline__ uint32_t smem_to_u32(const void* p) {
    uint32_t a;
    asm("{ .reg .u64 t; cvta.to.shared.u64 t, %1; cvt.u32.u64 %0, t; }" : "=r"(a) : "l"(p));
    return a;
}

__device__ __forceinline__ void ldm_x4(uint32_t* r, uint32_t addr) {
    asm volatile("ldmatrix.sync.aligned.m8n8.x4.shared.b16 {%0,%1,%2,%3}, [%4];"
                 : "=r"(r[0]), "=r"(r[1]), "=r"(r[2]), "=r"(r[3]) : "r"(addr));
}
__device__ __forceinline__ void ldm_x4_t(uint32_t* r, uint32_t addr) {
    asm volatile("ldmatrix.sync.aligned.m8n8.x4.trans.shared.b16 {%0,%1,%2,%3}, [%4];"
                 : "=r"(r[0]), "=r"(r[1]), "=r"(r[2]), "=r"(r[3]) : "r"(addr));
}

__device__ __forceinline__ void mma_bf16(float* c, const uint32_t* a, uint32_t b0, uint32_t b1) {
    asm volatile("mma.sync.aligned.m16n8k16.row.col.f32.bf16.bf16.f32 "
                 "{%0,%1,%2,%3}, {%4,%5,%6,%7}, {%8,%9}, {%0,%1,%2,%3};"
                 : "+f"(c[0]), "+f"(c[1]), "+f"(c[2]), "+f"(c[3])
                 : "r"(a[0]), "r"(a[1]), "r"(a[2]), "r"(a[3]), "r"(b0), "r"(b1));
}

#define CP_ASYNC16(saddr, gptr) \
    asm volatile("cp.async.cg.shared.global [%0], [%1], 16;" :: "r"(saddr), "l"(gptr))
#define CP_COMMIT() asm volatile("cp.async.commit_group;" ::: "memory")
#define CP_WAIT1()  asm volatile("cp.async.wait_group 1;" ::: "memory")
#define CP_WAIT0()  asm volatile("cp.async.wait_group 0;" ::: "memory")

__device__ __forceinline__ uint32_t cvt2bf(float hi, float lo) {
    uint32_t r;
    asm("cvt.rn.bf16x2.f32 %0, %1, %2;" : "=r"(r) : "f"(hi), "f"(lo));
    return r;
}

// MUFU exp2 (runs on MUFU pipe, overlaps tensor/fma)
__device__ __forceinline__ float ex2f(float x) {
    float y;
    asm("ex2.approx.f32 %0, %1;" : "=f"(y) : "f"(x));
    return y;
}

// =====================================================================
// fused fp32 -> bf16 (hi, lo) splits, z-indexed over inputs
// =====================================================================
__device__ __forceinline__ void split_one(const float* __restrict__ x,
                                          __nv_bfloat16* __restrict__ hi,
                                          __nv_bfloat16* __restrict__ lo, int i)
{
    float4 v = reinterpret_cast<const float4*>(x)[i];
    __nv_bfloat16 h0 = __float2bfloat16(v.x);
    __nv_bfloat16 h1 = __float2bfloat16(v.y);
    __nv_bfloat16 h2 = __float2bfloat16(v.z);
    __nv_bfloat16 h3 = __float2bfloat16(v.w);
    __nv_bfloat16 l0 = __float2bfloat16(v.x - __bfloat162float(h0));
    __nv_bfloat16 l1 = __float2bfloat16(v.y - __bfloat162float(h1));
    __nv_bfloat16 l2 = __float2bfloat16(v.z - __bfloat162float(h2));
    __nv_bfloat16 l3 = __float2bfloat16(v.w - __bfloat162float(h3));
    __nv_bfloat162* hp = reinterpret_cast<__nv_bfloat162*>(hi) + i * 2;
    __nv_bfloat162* lp = reinterpret_cast<__nv_bfloat162*>(lo) + i * 2;
    hp[0] = __nv_bfloat162(h0, h1);
    hp[1] = __nv_bfloat162(h2, h3);
    lp[0] = __nv_bfloat162(l0, l1);
    lp[1] = __nv_bfloat162(l2, l3);
}

__global__ __launch_bounds__(256)
void split3_kernel(const float* __restrict__ q, const float* __restrict__ k,
                   const float* __restrict__ v,
                   __nv_bfloat16* __restrict__ hi, __nv_bfloat16* __restrict__ lo)
{
    const int z = blockIdx.z;
    const float* x = (z == 0) ? q : (z == 1) ? k : v;
    int i = blockIdx.x * blockDim.x + threadIdx.x;
    split_one(x, hi + (size_t)z * ASZ, lo + (size_t)z * ASZ, i);
}

__global__ __launch_bounds__(256)
void split4_kernel(const float* __restrict__ w0, const float* __restrict__ w1,
                   const float* __restrict__ w2, const float* __restrict__ w3,
                   __nv_bfloat16* __restrict__ hi, __nv_bfloat16* __restrict__ lo)
{
    const int z = blockIdx.z;
    const float* x = (z == 0) ? w0 : (z == 1) ? w1 : (z == 2) ? w2 : w3;
    int i = blockIdx.x * blockDim.x + threadIdx.x;
    split_one(x, hi + (size_t)z * WSZ, lo + (size_t)z * WSZ, i);
}

// =====================================================================
// mma.sync GEMM core: 128x128 tile, BK=32, swizzled smem, 3-stage cp.async,
// 1 sync/chunk, 2 CTAs/SM. (R8 proven form, unchanged)
// =====================================================================
#define TERM_B    8192                 // 128 rows * 64 B
#define OFF_AH    0
#define OFF_AL    TERM_B
#define OFF_BH    (2 * TERM_B)
#define OFF_BL    (3 * TERM_B)
#define STAGE_B   (4 * TERM_B)         // 32768
#define NSTAGE    3
#define GEMM_SMEM (NSTAGE * STAGE_B + 128)   // 98432

__device__ __forceinline__ uint32_t swz(int row, int c) {
    return (uint32_t)(row * 64 + ((c ^ ((row >> 1) & 3)) << 4));
}

__device__ __forceinline__ void gemm_core(const __nv_bfloat16* __restrict__ Ah,
                                          const __nv_bfloat16* __restrict__ Al,
                                          const __nv_bfloat16* __restrict__ Bh,
                                          const __nv_bfloat16* __restrict__ Bl,
                                          const float* __restrict__ bias,
                                          __nv_bfloat16* __restrict__ Chi,
                                          __nv_bfloat16* __restrict__ Clo,
                                          float* __restrict__ Cf,
                                          char* sm, int bm, int bn)
{
    const uint32_t smb = (smem_to_u32(sm) + 127u) & ~127u;
    const int tid  = threadIdx.x;
    const int lane = tid & 31;
    const int wid  = tid >> 5;
    const int warp_m = wid >> 2;
    const int warp_n = wid & 3;

    float acc[4][4][4];
#pragma unroll
    for (int mi = 0; mi < 4; ++mi)
#pragma unroll
        for (int nj = 0; nj < 4; ++nj)
#pragma unroll
            for (int e = 0; e < 4; ++e) acc[mi][nj][e] = 0.f;

    auto issue = [&](int c, int j) {
        const int koff = c * 32;
        const uint32_t sb = smb + (uint32_t)j * STAGE_B;
#pragma unroll
        for (int u = tid; u < 512; u += 256) {
            const int row = u >> 2, cc = u & 3;
            const uint32_t so = swz(row, cc);
            const size_t gA = (size_t)(bm + row) * D_MODEL + koff + cc * 8;
            const size_t gB = (size_t)(bn + row) * D_MODEL + koff + cc * 8;
            CP_ASYNC16(sb + OFF_AH + so, Ah + gA);
            CP_ASYNC16(sb + OFF_AL + so, Al + gA);
            CP_ASYNC16(sb + OFF_BH + so, Bh + gB);
            CP_ASYNC16(sb + OFF_BL + so, Bl + gB);
        }
        CP_COMMIT();
    };

    const int rA = lane & 15, cA = lane >> 4;
    const uint32_t aoff = swz(rA, cA);
    const int rB = (lane & 7) | ((lane >> 4) << 3), cB = (lane >> 3) & 1;
    const uint32_t boff = swz(rB, cB);

    const uint32_t aH_base = smb + OFF_AH + (uint32_t)(warp_m * 4096) + aoff;
    const uint32_t aL_base = smb + OFF_AL + (uint32_t)(warp_m * 4096) + aoff;
    const uint32_t bH_base = smb + OFF_BH + (uint32_t)(warp_n * 2048) + boff;
    const uint32_t bL_base = smb + OFF_BL + (uint32_t)(warp_n * 2048) + boff;

    const int NCHUNK = D_MODEL / 32;
    issue(0, 0);
    issue(1, 1);

    for (int c = 0; c < NCHUNK; ++c) {
        const int j = c % NSTAGE;
        if (c + 1 < NCHUNK) { CP_WAIT1(); } else { CP_WAIT0(); }
        __syncthreads();
        if (c + 2 < NCHUNK) issue(c + 2, (c + 2) % NSTAGE);

        const uint32_t stg = (uint32_t)j * STAGE_B;
#pragma unroll
        for (int ks = 0; ks < 2; ++ks) {
            const uint32_t kx = (uint32_t)(ks << 5);
            uint32_t ah[4][4], al[4][4], bhv[4][2], blv[4][2];
#pragma unroll
            for (int mi = 0; mi < 4; ++mi) {
                ldm_x4(ah[mi], (aH_base + stg + (uint32_t)(mi * 1024)) ^ kx);
                ldm_x4(al[mi], (aL_base + stg + (uint32_t)(mi * 1024)) ^ kx);
            }
#pragma unroll
            for (int p = 0; p < 2; ++p) {
                uint32_t r[4];
                ldm_x4(r, (bH_base + stg + (uint32_t)(p * 1024)) ^ kx);
                bhv[p * 2 + 0][0] = r[0]; bhv[p * 2 + 0][1] = r[1];
                bhv[p * 2 + 1][0] = r[2]; bhv[p * 2 + 1][1] = r[3];
                ldm_x4(r, (bL_base + stg + (uint32_t)(p * 1024)) ^ kx);
                blv[p * 2 + 0][0] = r[0]; blv[p * 2 + 0][1] = r[1];
                blv[p * 2 + 1][0] = r[2]; blv[p * 2 + 1][1] = r[3];
            }
#pragma unroll
            for (int mi = 0; mi < 4; ++mi)
#pragma unroll
                for (int nj = 0; nj < 4; ++nj)
                    mma_bf16(acc[mi][nj], ah[mi], bhv[nj][0], bhv[nj][1]);
#pragma unroll
            for (int mi = 0; mi < 4; ++mi)
#pragma unroll
                for (int nj = 0; nj < 4; ++nj)
                    mma_bf16(acc[mi][nj], ah[mi], blv[nj][0], blv[nj][1]);
#pragma unroll
            for (int mi = 0; mi < 4; ++mi)
#pragma unroll
                for (int nj = 0; nj < 4; ++nj)
                    mma_bf16(acc[mi][nj], al[mi], bhv[nj][0], bhv[nj][1]);
        }
    }

    const int rbase = bm + warp_m * 64;
    const int cbase = bn + warp_n * 32;
#pragma unroll
    for (int mi = 0; mi < 4; ++mi) {
#pragma unroll
        for (int nj = 0; nj < 4; ++nj) {
            const int r0 = rbase + mi * 16 + (lane >> 2);
            const int cc = cbase + nj * 8 + 2 * (lane & 3);
            const float b0 = bias[cc], b1 = bias[cc + 1];
            const float v0 = acc[mi][nj][0] + b0, v1 = acc[mi][nj][1] + b1;
            const float v2 = acc[mi][nj][2] + b0, v3 = acc[mi][nj][3] + b1;
            if (Cf) {
                float2 w0, w1;
                w0.x = v0; w0.y = v1; w1.x = v2; w1.y = v3;
                *reinterpret_cast<float2*>(Cf + (size_t)r0 * D_MODEL + cc) = w0;
                *reinterpret_cast<float2*>(Cf + (size_t)(r0 + 8) * D_MODEL + cc) = w1;
            } else {
                uint32_t hp0 = cvt2bf(v1, v0);
                uint32_t hp1 = cvt2bf(v3, v2);
                float h0 = __uint_as_float(hp0 << 16), h1 = __uint_as_float(hp0 & 0xFFFF0000u);
                float h2 = __uint_as_float(hp1 << 16), h3 = __uint_as_float(hp1 & 0xFFFF0000u);
                uint32_t lp0 = cvt2bf(v1 - h1, v0 - h0);
                uint32_t lp1 = cvt2bf(v3 - h3, v2 - h2);
                *reinterpret_cast<uint32_t*>(Chi + (size_t)r0 * D_MODEL + cc) = hp0;
                *reinterpret_cast<uint32_t*>(Chi + (size_t)(r0 + 8) * D_MODEL + cc) = hp1;
                *reinterpret_cast<uint32_t*>(Clo + (size_t)r0 * D_MODEL + cc) = lp0;
                *reinterpret_cast<uint32_t*>(Clo + (size_t)(r0 + 8) * D_MODEL + cc) = lp1;
            }
        }
    }
}

__global__ __launch_bounds__(256, 2)
void gemm_qkv_kernel(const __nv_bfloat16* __restrict__ Ah3, const __nv_bfloat16* __restrict__ Al3,
                     const __nv_bfloat16* __restrict__ Wh4, const __nv_bfloat16* __restrict__ Wl4,
                     const float* __restrict__ bq, const float* __restrict__ bk,
                     const float* __restrict__ bv,
                     __nv_bfloat16* __restrict__ Qh, __nv_bfloat16* __restrict__ Ql,
                     __nv_bfloat16* __restrict__ Kh, __nv_bfloat16* __restrict__ Kl,
                     __nv_bfloat16* __restrict__ Vh, __nv_bfloat16* __restrict__ Vl)
{
    extern __shared__ char sm[];
    const int z = blockIdx.z;
    const float* bias = (z == 0) ? bq : (z == 1) ? bk : bv;
    __nv_bfloat16* Chi = (z == 0) ? Qh : (z == 1) ? Kh : Vh;
    __nv_bfloat16* Clo = (z == 0) ? Ql : (z == 1) ? Kl : Vl;
    gemm_core(Ah3 + (size_t)z * ASZ, Al3 + (size_t)z * ASZ,
              Wh4 + (size_t)z * WSZ, Wl4 + (size_t)z * WSZ,
              bias, Chi, Clo, nullptr, sm, blockIdx.y * 128, blockIdx.x * 128);
}

__global__ __launch_bounds__(256, 2)
void gemm_out_kernel(const __nv_bfloat16* __restrict__ Ah, const __nv_bfloat16* __restrict__ Al,
                     const __nv_bfloat16* __restrict__ Bh, const __nv_bfloat16* __restrict__ Bl,
                     const float* __restrict__ bias, float* __restrict__ Cf)
{
    extern __shared__ char sm[];
    gemm_core(Ah, Al, Bh, Bl, bias, nullptr, nullptr, Cf,
              sm, blockIdx.y * 128, blockIdx.x * 128);
}

// =====================================================================
// mma.sync flash attention — paired q-blocks, max-free softmax,
// half-tile software pipeline (QK0|sm0|QK1|sm1|PV0|PV1) + causal
// per-warp half-tile skips.
// =====================================================================
#define QTERM_B  18432               // 128*72*2
#define KVARR_B  9216                // 64*72*2
#define STG_B    (4 * KVARR_B + 256)
#define FL_SMEM  (2 * QTERM_B + 2 * STG_B)   // 111104
#define SCL2E    0.180336879f        // 0.125 * log2(e)
#define NQB      (T_ / 128)          // 16

__global__ __launch_bounds__(256, 2)
void flash_tc_kernel(const __nv_bfloat16* __restrict__ Qh_g, const __nv_bfloat16* __restrict__ Ql_g,
                     const __nv_bfloat16* __restrict__ Kh_g, const __nv_bfloat16* __restrict__ Kl_g,
                     const __nv_bfloat16* __restrict__ Vh_g, const __nv_bfloat16* __restrict__ Vl_g,
                     const int* __restrict__ mask, const int* __restrict__ causal_p,
                     __nv_bfloat16* __restrict__ Oh_g, __nv_bfloat16* __restrict__ Ol_g)
{
    extern __shared__ char smc[];
    const uint32_t smb = smem_to_u32(smc);
    const int tid = threadIdx.x, lane = tid & 31, warp = tid >> 5;
    const int pair = blockIdx.x;                 // 0..7
    const int bh = blockIdx.y, b = bh >> 4, h = bh & 15;
    const int causal = *causal_p;

    auto issue_kv = [&](int kt, int s) {
        const uint32_t sb = smb + 2u * QTERM_B + (uint32_t)s * STG_B;
        const int tk0 = b * T_ + kt * 64;
#pragma unroll
        for (int u = tid; u < 2048; u += 256) {
            const int arr = u >> 9, rem = u & 511;
            const int row = rem >> 3, c = rem & 7;
            const __nv_bfloat16* base = (arr == 0) ? Kh_g : (arr == 1) ? Kl_g
                                       : (arr == 2) ? Vh_g : Vl_g;
            CP_ASYNC16(sb + (uint32_t)(arr * KVARR_B + row * 144 + c * 16),
                       base + ((size_t)(tk0 + row) * D_MODEL + h * 64 + c * 8));
        }
        if (tid < 64) {
            float mv = (mask[tk0 + tid] == 0) ? -1e30f : 0.f;
            reinterpret_cast<float*>(smc + 2 * QTERM_B + s * STG_B + 4 * KVARR_B)[tid] = mv;
        }
    };

    const uint32_t a_lane = (uint32_t)((lane & 15) * 144 + (lane >> 4) * 16);
    const uint32_t b_lane = (uint32_t)(((lane & 7) + ((lane >> 4) << 3)) * 144 + ((lane >> 3) & 1) * 16);
    const uint32_t qsH = smb + (uint32_t)(warp * 16 * 144) + a_lane;
    const uint32_t qsL = qsH + QTERM_B;
    const int r_in_warp = lane >> 2;
    const int colb = 2 * (lane & 3);

    for (int blk = 0; blk < 2; ++blk) {
        const int qb = (blk == 0) ? (NQB - 1 - pair) : pair;   // big block first
        const int kend = causal ? (2 * qb + 1) : (T_ / 64 - 1);
        const int rowg0 = b * T_ + qb * 128;
        const int maxrow = qb * 128 + warp * 16 + 15;   // last q row this warp owns

        __syncthreads();   // all reads of previous block's Q smem are done

        {
#pragma unroll
            for (int u = tid; u < 2048; u += 256) {
                const int term = u >> 10, rem = u & 1023;
                const int row = rem >> 3, c = rem & 7;
                const __nv_bfloat16* src = (term ? Ql_g : Qh_g)
                    + ((size_t)(rowg0 + row) * D_MODEL + h * 64 + c * 8);
                CP_ASYNC16(smb + (uint32_t)(term * QTERM_B + row * 144 + c * 16), src);
            }
            issue_kv(0, 0);
            CP_COMMIT();
        }

        uint32_t qhf[4][4];
        float o[8][4];
#pragma unroll
        for (int nd = 0; nd < 8; ++nd)
#pragma unroll
            for (int e = 0; e < 4; ++e) o[nd][e] = 0.f;
        float l0 = 0.f, l1 = 0.f;

        const int rg0 = qb * 128 + warp * 16 + r_in_warp;
        const int rg1 = rg0 + 8;

        for (int kt = 0; kt <= kend; ++kt) {
            CP_WAIT0();
            __syncthreads();
            if (kt + 1 <= kend) { issue_kv(kt + 1, (kt + 1) & 1); CP_COMMIT(); }

            if (kt == 0) {
#pragma unroll
                for (int ks = 0; ks < 4; ++ks)
                    ldm_x4(qhf[ks], qsH + (uint32_t)(ks * 32));
            }

            const int j = kt & 1;
            const uint32_t sb = smb + 2u * QTERM_B + (uint32_t)j * STG_B;
            const float* madd = reinterpret_cast<const float*>(smc + 2 * QTERM_B + j * STG_B + 4 * KVARR_B);

            const bool diag = (causal != 0) && (kt >= 2 * qb);
            // half h entirely above the diagonal for this warp's rows?
            const bool skip0 = diag && (kt * 64      > maxrow);
            const bool skip1 = diag && (kt * 64 + 32 > maxrow);

            float c[8][4];
#pragma unroll
            for (int nj = 0; nj < 8; ++nj)
#pragma unroll
                for (int e = 0; e < 4; ++e) c[nj][e] = 0.f;

            // ---- QK half 0 (KV rows 0..31 -> c[0..3]) ----
            if (!skip0) {
#pragma unroll
                for (int ks = 0; ks < 4; ++ks) {
                    const uint32_t kb = (uint32_t)(ks * 32);
                    uint32_t qlf[4];
                    ldm_x4(qlf, qsL + kb);
                    uint32_t rh[2][4], rl[2][4];
                    const uint32_t kb0 = sb + b_lane + kb;
                    ldm_x4(rh[0], kb0);
                    ldm_x4(rl[0], kb0 + KVARR_B);
                    ldm_x4(rh[1], kb0 + 2304u);
                    ldm_x4(rl[1], kb0 + 2304u + KVARR_B);
                    mma_bf16(c[0], qhf[ks], rh[0][0], rh[0][1]);
                    mma_bf16(c[1], qhf[ks], rh[0][2], rh[0][3]);
                    mma_bf16(c[2], qhf[ks], rh[1][0], rh[1][1]);
                    mma_bf16(c[3], qhf[ks], rh[1][2], rh[1][3]);
                    mma_bf16(c[0], qhf[ks], rl[0][0], rl[0][1]);
                    mma_bf16(c[1], qhf[ks], rl[0][2], rl[0][3]);
                    mma_bf16(c[2], qhf[ks], rl[1][0], rl[1][1]);
                    mma_bf16(c[3], qhf[ks], rl[1][2], rl[1][3]);
                    mma_bf16(c[0], qlf, rh[0][0], rh[0][1]);
                    mma_bf16(c[1], qlf, rh[0][2], rh[0][3]);
                    mma_bf16(c[2], qlf, rh[1][0], rh[1][1]);
                    mma_bf16(c[3], qlf, rh[1][2], rh[1][3]);
                }
                // ---- softmax half 0 (independent of QK half 1 below) ----
#pragma unroll
                for (int nj = 0; nj < 4; ++nj) {
                    const int cl = nj * 8 + colb;
                    const int cg = kt * 64 + cl;
                    const float ma0 = madd[cl], ma1 = madd[cl + 1];
                    float s0 = fmaf(c[nj][0], SCL2E, ma0);
                    float s1 = fmaf(c[nj][1], SCL2E, ma1);
                    float s2 = fmaf(c[nj][2], SCL2E, ma0);
                    float s3 = fmaf(c[nj][3], SCL2E, ma1);
                    if (diag) {
                        if (cg > rg0)     s0 = -1e30f;
                        if (cg + 1 > rg0) s1 = -1e30f;
                        if (cg > rg1)     s2 = -1e30f;
                        if (cg + 1 > rg1) s3 = -1e30f;
                    }
                    float p0 = ex2f(s0);
                    float p1 = ex2f(s1);
                    float p2 = ex2f(s2);
                    float p3 = ex2f(s3);
                    c[nj][0] = p0; c[nj][1] = p1; c[nj][2] = p2; c[nj][3] = p3;
                    l0 += p0 + p1; l1 += p2 + p3;
                }
            }

            // ---- QK half 1 (KV rows 32..63 -> c[4..7]) ----
            if (!skip1) {
#pragma unroll
                for (int ks = 0; ks < 4; ++ks) {
                    const uint32_t kb = (uint32_t)(ks * 32);
                    uint32_t qlf[4];
                    ldm_x4(qlf, qsL + kb);
                    uint32_t rh[2][4], rl[2][4];
                    const uint32_t kb0 = sb + b_lane + 2u * 2304u + kb;
                    ldm_x4(rh[0], kb0);
                    ldm_x4(rl[0], kb0 + KVARR_B);
                    ldm_x4(rh[1], kb0 + 2304u);
                    ldm_x4(rl[1], kb0 + 2304u + KVARR_B);
                    mma_bf16(c[4], qhf[ks], rh[0][0], rh[0][1]);
                    mma_bf16(c[5], qhf[ks], rh[0][2], rh[0][3]);
                    mma_bf16(c[6], qhf[ks], rh[1][0], rh[1][1]);
                    mma_bf16(c[7], qhf[ks], rh[1][2], rh[1][3]);
                    mma_bf16(c[4], qhf[ks], rl[0][0], rl[0][1]);
                    mma_bf16(c[5], qhf[ks], rl[0][2], rl[0][3]);
                    mma_bf16(c[6], qhf[ks], rl[1][0], rl[1][1]);
                    mma_bf16(c[7], qhf[ks], rl[1][2], rl[1][3]);
                    mma_bf16(c[4], qlf, rh[0][0], rh[0][1]);
                    mma_bf16(c[5], qlf, rh[0][2], rh[0][3]);
                    mma_bf16(c[6], qlf, rh[1][0], rh[1][1]);
                    mma_bf16(c[7], qlf, rh[1][2], rh[1][3]);
                }
                // ---- softmax half 1 (independent of PV half 0 below) ----
#pragma unroll
                for (int nj = 4; nj < 8; ++nj) {
                    const int cl = nj * 8 + colb;
                    const int cg = kt * 64 + cl;
                    const float ma0 = madd[cl], ma1 = madd[cl + 1];
                    float s0 = fmaf(c[nj][0], SCL2E, ma0);
                    float s1 = fmaf(c[nj][1], SCL2E, ma1);
                    float s2 = fmaf(c[nj][2], SCL2E, ma0);
                    float s3 = fmaf(c[nj][3], SCL2E, ma1);
                    if (diag) {
                        if (cg > rg0)     s0 = -1e30f;
                        if (cg + 1 > rg0) s1 = -1e30f;
                        if (cg > rg1)     s2 = -1e30f;
                        if (cg + 1 > rg1) s3 = -1e30f;
                    }
                    float p0 = ex2f(s0);
                    float p1 = ex2f(s1);
                    float p2 = ex2f(s2);
                    float p3 = ex2f(s3);
                    c[nj][0] = p0; c[nj][1] = p1; c[nj][2] = p2; c[nj][3] = p3;
                    l0 += p0 + p1; l1 += p2 + p3;
                }
            }

            // ---- PV half 0 (KV rows 0..31 = ks 0,1) ----
            if (!skip0) {
#pragma unroll
                for (int ks = 0; ks < 2; ++ks) {
                    uint32_t pfh[4], pfl[4];
#pragma unroll
                    for (int half = 0; half < 2; ++half) {
                        const int nj = 2 * ks + half;
                        uint32_t hpA = cvt2bf(c[nj][1], c[nj][0]);
                        uint32_t hpB = cvt2bf(c[nj][3], c[nj][2]);
                        float hA0 = __uint_as_float(hpA << 16), hA1 = __uint_as_float(hpA & 0xFFFF0000u);
                        float hB0 = __uint_as_float(hpB << 16), hB1 = __uint_as_float(hpB & 0xFFFF0000u);
                        pfh[2 * half + 0] = hpA; pfh[2 * half + 1] = hpB;
                        pfl[2 * half + 0] = cvt2bf(c[nj][1] - hA1, c[nj][0] - hA0);
                        pfl[2 * half + 1] = cvt2bf(c[nj][3] - hB1, c[nj][2] - hB0);
                    }
#pragma unroll
                    for (int np = 0; np < 2; ++np) {
                        uint32_t vh[2][4], vl[2][4];
                        const uint32_t va = sb + 2u * KVARR_B + a_lane
                                          + (uint32_t)(ks * 16 * 144) + (uint32_t)((2 * np) * 32);
                        ldm_x4_t(vh[0], va);
                        ldm_x4_t(vl[0], va + KVARR_B);
                        ldm_x4_t(vh[1], va + 32u);
                        ldm_x4_t(vl[1], va + 32u + KVARR_B);
                        float* o0 = o[4 * np + 0];
                        float* o1 = o[4 * np + 1];
                        float* o2 = o[4 * np + 2];
                        float* o3 = o[4 * np + 3];
                        mma_bf16(o0, pfh, vh[0][0], vh[0][1]);
                        mma_bf16(o1, pfh, vh[0][2], vh[0][3]);
                        mma_bf16(o2, pfh, vh[1][0], vh[1][1]);
                        mma_bf16(o3, pfh, vh[1][2], vh[1][3]);
                        mma_bf16(o0, pfh, vl[0][0], vl[0][1]);
                        mma_bf16(o1, pfh, vl[0][2], vl[0][3]);
                        mma_bf16(o2, pfh, vl[1][0], vl[1][1]);
                        mma_bf16(o3, pfh, vl[1][2], vl[1][3]);
                        mma_bf16(o0, pfl, vh[0][0], vh[0][1]);
                        mma_bf16(o1, pfl, vh[0][2], vh[0][3]);
                        mma_bf16(o2, pfl, vh[1][0], vh[1][1]);
                        mma_bf16(o3, pfl, vh[1][2], vh[1][3]);
                    }
                }
            }

            // ---- PV half 1 (KV rows 32..63 = ks 2,3) ----
            if (!skip1) {
#pragma unroll
                for (int ks = 2; ks < 4; ++ks) {
                    uint32_t pfh[4], pfl[4];
#pragma unroll
                    for (int half = 0; half < 2; ++half) {
                        const int nj = 2 * ks + half;
                        uint32_t hpA = cvt2bf(c[nj][1], c[nj][0]);
                        uint32_t hpB = cvt2bf(c[nj][3], c[nj][2]);
                        float hA0 = __uint_as_float(hpA << 16), hA1 = __uint_as_float(hpA & 0xFFFF0000u);
                        float hB0 = __uint_as_float(hpB << 16), hB1 = __uint_as_float(hpB & 0xFFFF0000u);
                        pfh[2 * half + 0] = hpA; pfh[2 * half + 1] = hpB;
                        pfl[2 * half + 0] = cvt2bf(c[nj][1] - hA1, c[nj][0] - hA0);
                        pfl[2 * half + 1] = cvt2bf(c[nj][3] - hB1, c[nj][2] - hB0);
                    }
#pragma unroll
                    for (int np = 0; np < 2; ++np) {
                        uint32_t vh[2][4], vl[2][4];
                        const uint32_t va = sb + 2u * KVARR_B + a_lane
                                          + (uint32_t)(ks * 16 * 144) + (uint32_t)((2 * np) * 32);
                        ldm_x4_t(vh[0], va);
                        ldm_x4_t(vl[0], va + KVARR_B);
                        ldm_x4_t(vh[1], va + 32u);
                        ldm_x4_t(vl[1], va + 32u + KVARR_B);
                        float* o0 = o[4 * np + 0];
                        float* o1 = o[4 * np + 1];
                        float* o2 = o[4 * np + 2];
                        float* o3 = o[4 * np + 3];
                        mma_bf16(o0, pfh, vh[0][0], vh[0][1]);
                        mma_bf16(o1, pfh, vh[0][2], vh[0][3]);
                        mma_bf16(o2, pfh, vh[1][0], vh[1][1]);
                        mma_bf16(o3, pfh, vh[1][2], vh[1][3]);
                        mma_bf16(o0, pfh, vl[0][0], vl[0][1]);
                        mma_bf16(o1, pfh, vl[0][2], vl[0][3]);
                        mma_bf16(o2, pfh, vl[1][0], vl[1][1]);
                        mma_bf16(o3, pfh, vl[1][2], vl[1][3]);
                        mma_bf16(o0, pfl, vh[0][0], vh[0][1]);
                        mma_bf16(o1, pfl, vh[0][2], vh[0][3]);
                        mma_bf16(o2, pfl, vh[1][0], vh[1][1]);
                        mma_bf16(o3, pfl, vh[1][2], vh[1][3]);
                    }
                }
            }
        }

        // ---- epilogue: reduce row sums across quad lanes, normalize ----
        l0 += __shfl_xor_sync(0xffffffffu, l0, 1);
        l0 += __shfl_xor_sync(0xffffffffu, l0, 2);
        l1 += __shfl_xor_sync(0xffffffffu, l1, 1);
        l1 += __shfl_xor_sync(0xffffffffu, l1, 2);
        const float inv0 = __fdividef(1.f, l0);
        const float inv1 = __fdividef(1.f, l1);
        const size_t gr0 = (size_t)(rowg0 + warp * 16 + r_in_warp) * D_MODEL + h * 64;
        const size_t gr1 = gr0 + 8 * D_MODEL;
#pragma unroll
        for (int nd = 0; nd < 8; ++nd) {
            const int cc = nd * 8 + colb;
            float v0 = o[nd][0] * inv0, v1 = o[nd][1] * inv0;
            float v2 = o[nd][2] * inv1, v3 = o[nd][3] * inv1;
            uint32_t hp0 = cvt2bf(v1, v0);
            uint32_t hp1 = cvt2bf(v3, v2);
            float h0 = __uint_as_float(hp0 << 16), h1 = __uint_as_float(hp0 & 0xFFFF0000u);
            float h2 = __uint_as_float(hp1 << 16), h3 = __uint_as_float(hp1 & 0xFFFF0000u);
            uint32_t lp0 = cvt2bf(v1 - h1, v0 - h0);
            uint32_t lp1 = cvt2bf(v3 - h3, v2 - h2);
            *reinterpret_cast<uint32_t*>(Oh_g + gr0 + cc) = hp0;
            *reinterpret_cast<uint32_t*>(Oh_g + gr1 + cc) = hp1;
            *reinterpret_cast<uint32_t*>(Ol_g + gr0 + cc) = lp0;
            *reinterpret_cast<uint32_t*>(Ol_g + gr1 + cc) = lp1;
        }
    }
}

// =====================================================================
// launch
// =====================================================================
extern "C" void kernel_launch(void* const* d_in, const int* in_sizes, int n_in,
                              void* d_out, int out_size)
{
    const float* q    = (const float*)d_in[0];
    const float* k    = (const float*)d_in[1];
    const float* v    = (const float*)d_in[2];
    const float* Wq   = (const float*)d_in[3];
    const float* bq   = (const float*)d_in[4];
    const float* Wk   = (const float*)d_in[5];
    const float* bk   = (const float*)d_in[6];
    const float* Wv   = (const float*)d_in[7];
    const float* bv   = (const float*)d_in[8];
    const float* Wo   = (const float*)d_in[9];
    const float* bo   = (const float*)d_in[10];
    const int*   mask = (const int*)d_in[11];
    const int*   causal = (const int*)d_in[12];
    float* out = (float*)d_out;

    __nv_bfloat16 *Ah, *Al, *Wh, *Wl, *Qh, *Ql, *Kh, *Kl, *Vh, *Vl, *Anh, *Anl;
    cudaGetSymbolAddress((void**)&Ah, g_Ah);
    cudaGetSymbolAddress((void**)&Al, g_Al);
    cudaGetSymbolAddress((void**)&Wh, g_Wh);
    cudaGetSymbolAddress((void**)&Wl, g_Wl);
    cudaGetSymbolAddress((void**)&Qh, g_Qh);
    cudaGetSymbolAddress((void**)&Ql, g_Ql);
    cudaGetSymbolAddress((void**)&Kh, g_Kh);
    cudaGetSymbolAddress((void**)&Kl, g_Kl);
    cudaGetSymbolAddress((void**)&Vh, g_Vh);
    cudaGetSymbolAddress((void**)&Vl, g_Vl);
    cudaGetSymbolAddress((void**)&Anh, g_Anh);
    cudaGetSymbolAddress((void**)&Anl, g_Anl);

    cudaFuncSetAttribute(gemm_qkv_kernel,
                         cudaFuncAttributeMaxDynamicSharedMemorySize, GEMM_SMEM);
    cudaFuncSetAttribute(gemm_out_kernel,
                         cudaFuncAttributeMaxDynamicSharedMemorySize, GEMM_SMEM);
    cudaFuncSetAttribute(flash_tc_kernel,
                         cudaFuncAttributeMaxDynamicSharedMemorySize, FL_SMEM);

    const int nA4 = ASZ / 4;
    const int nW4 = WSZ / 4;

    split3_kernel<<<dim3(nA4 / 256, 1, 3), 256>>>(q, k, v, Ah, Al);
    split4_kernel<<<dim3(nW4 / 256, 1, 4), 256>>>(Wq, Wk, Wv, Wo, Wh, Wl);

    gemm_qkv_kernel<<<dim3(D_MODEL / 128, M_ROWS / 128, 3), 256, GEMM_SMEM>>>(
        Ah, Al, Wh, Wl, bq, bk, bv, Qh, Ql, Kh, Kl, Vh, Vl);

    dim3 fgrid(NQB / 2, B_ * N_HEADS);   // (8, 32) = 256 CTAs, one balanced wave
    flash_tc_kernel<<<fgrid, 256, FL_SMEM>>>(Qh, Ql, Kh, Kl, Vh, Vl, mask, causal, Anh, Anl);

    gemm_out_kernel<<<dim3(D_MODEL / 128, M_ROWS / 128), 256, GEMM_SMEM>>>(
        Anh, Anl, Wh + (size_t)3 * WSZ, Wl + (size_t)3 * WSZ, bo, out);
}

// round 17
// speedup vs baseline: 1.0436x; 1.0436x over previous
#include <cuda_runtime.h>
#include <cuda_bf16.h>
#include <cstdint>

#define D_MODEL 1024
#define N_HEADS 16
#define D_K     64
#define B_      2
#define T_      2048
#define M_ROWS  (B_ * T_)      // 4096
#define ASZ     (M_ROWS * D_MODEL)
#define WSZ     (D_MODEL * D_MODEL)

// ---------------- scratch (static device globals: allowed) ----------------
__device__ __nv_bfloat16 g_Ah[3 * ASZ];
__device__ __nv_bfloat16 g_Al[3 * ASZ];
__device__ __nv_bfloat16 g_Wh[4 * WSZ];
__device__ __nv_bfloat16 g_Wl[4 * WSZ];
__device__ __nv_bfloat16 g_Qh[ASZ];
__device__ __nv_bfloat16 g_Ql[ASZ];
__device__ __nv_bfloat16 g_Kh[ASZ];
__device__ __nv_bfloat16 g_Kl[ASZ];
__device__ __nv_bfloat16 g_Vh[ASZ];
__device__ __nv_bfloat16 g_Vl[ASZ];
__device__ __nv_bfloat16 g_Anh[ASZ];
__device__ __nv_bfloat16 g_Anl[ASZ];

// =====================================================================
// portable tensor-core helpers (valid on plain sm_103 target)
// =====================================================================
__device__ __forceinline__ uint32_t smem_to_u32(const void* p) {
    uint32_t a;
    asm("{ .reg .u64 t; cvta.to.shared.u64 t, %1; cvt.u32.u64 %0, t; }" : "=r"(a) : "l"(p));
    return a;
}

__device__ __forceinline__ void ldm_x4(uint32_t* r, uint32_t addr) {
    asm volatile("ldmatrix.sync.aligned.m8n8.x4.shared.b16 {%0,%1,%2,%3}, [%4];"
                 : "=r"(r[0]), "=r"(r[1]), "=r"(r[2]), "=r"(r[3]) : "r"(addr));
}
__device__ __forceinline__ void ldm_x4_t(uint32_t* r, uint32_t addr) {
    asm volatile("ldmatrix.sync.aligned.m8n8.x4.trans.shared.b16 {%0,%1,%2,%3}, [%4];"
                 : "=r"(r[0]), "=r"(r[1]), "=r"(r[2]), "=r"(r[3]) : "r"(addr));
}

__device__ __forceinline__ void mma_bf16(float* c, const uint32_t* a, uint32_t b0, uint32_t b1) {
    asm volatile("mma.sync.aligned.m16n8k16.row.col.f32.bf16.bf16.f32 "
                 "{%0,%1,%2,%3}, {%4,%5,%6,%7}, {%8,%9}, {%0,%1,%2,%3};"
                 : "+f"(c[0]), "+f"(c[1]), "+f"(c[2]), "+f"(c[3])
                 : "r"(a[0]), "r"(a[1]), "r"(a[2]), "r"(a[3]), "r"(b0), "r"(b1));
}

#define CP_ASYNC16(saddr, gptr) \
    asm volatile("cp.async.cg.shared.global [%0], [%1], 16;" :: "r"(saddr), "l"(gptr))
#define CP_COMMIT() asm volatile("cp.async.commit_group;" ::: "memory")
#define CP_WAIT1()  asm volatile("cp.async.wait_group 1;" ::: "memory")
#define CP_WAIT0()  asm volatile("cp.async.wait_group 0;" ::: "memory")

__device__ __forceinline__ uint32_t cvt2bf(float hi, float lo) {
    uint32_t r;
    asm("cvt.rn.bf16x2.f32 %0, %1, %2;" : "=r"(r) : "f"(hi), "f"(lo));
    return r;
}

// MUFU exp2 (runs on MUFU pipe, overlaps tensor/fma)
__device__ __forceinline__ float ex2f(float x) {
    float y;
    asm("ex2.approx.f32 %0, %1;" : "=f"(y) : "f"(x));
    return y;
}

// =====================================================================
// fused fp32 -> bf16 (hi, lo) splits, z-indexed over inputs
// =====================================================================
__device__ __forceinline__ void split_one(const float* __restrict__ x,
                                          __nv_bfloat16* __restrict__ hi,
                                          __nv_bfloat16* __restrict__ lo, int i)
{
    float4 v = reinterpret_cast<const float4*>(x)[i];
    __nv_bfloat16 h0 = __float2bfloat16(v.x);
    __nv_bfloat16 h1 = __float2bfloat16(v.y);
    __nv_bfloat16 h2 = __float2bfloat16(v.z);
    __nv_bfloat16 h3 = __float2bfloat16(v.w);
    __nv_bfloat16 l0 = __float2bfloat16(v.x - __bfloat162float(h0));
    __nv_bfloat16 l1 = __float2bfloat16(v.y - __bfloat162float(h1));
    __nv_bfloat16 l2 = __float2bfloat16(v.z - __bfloat162float(h2));
    __nv_bfloat16 l3 = __float2bfloat16(v.w - __bfloat162float(h3));
    __nv_bfloat162* hp = reinterpret_cast<__nv_bfloat162*>(hi) + i * 2;
    __nv_bfloat162* lp = reinterpret_cast<__nv_bfloat162*>(lo) + i * 2;
    hp[0] = __nv_bfloat162(h0, h1);
    hp[1] = __nv_bfloat162(h2, h3);
    lp[0] = __nv_bfloat162(l0, l1);
    lp[1] = __nv_bfloat162(l2, l3);
}

__global__ __launch_bounds__(256)
void split3_kernel(const float* __restrict__ q, const float* __restrict__ k,
                   const float* __restrict__ v,
                   __nv_bfloat16* __restrict__ hi, __nv_bfloat16* __restrict__ lo)
{
    const int z = blockIdx.z;
    const float* x = (z == 0) ? q : (z == 1) ? k : v;
    int i = blockIdx.x * blockDim.x + threadIdx.x;
    split_one(x, hi + (size_t)z * ASZ, lo + (size_t)z * ASZ, i);
}

__global__ __launch_bounds__(256)
void split4_kernel(const float* __restrict__ w0, const float* __restrict__ w1,
                   const float* __restrict__ w2, const float* __restrict__ w3,
                   __nv_bfloat16* __restrict__ hi, __nv_bfloat16* __restrict__ lo)
{
    const int z = blockIdx.z;
    const float* x = (z == 0) ? w0 : (z == 1) ? w1 : (z == 2) ? w2 : w3;
    int i = blockIdx.x * blockDim.x + threadIdx.x;
    split_one(x, hi + (size_t)z * WSZ, lo + (size_t)z * WSZ, i);
}

// =====================================================================
// mma.sync GEMM core: 128x128 tile, BK=32, swizzled smem, 3-stage cp.async,
// 1 sync/chunk, 2 CTAs/SM. (R8 proven form, unchanged)
// =====================================================================
#define TERM_B    8192                 // 128 rows * 64 B
#define OFF_AH    0
#define OFF_AL    TERM_B
#define OFF_BH    (2 * TERM_B)
#define OFF_BL    (3 * TERM_B)
#define STAGE_B   (4 * TERM_B)         // 32768
#define NSTAGE    3
#define GEMM_SMEM (NSTAGE * STAGE_B + 128)   // 98432

__device__ __forceinline__ uint32_t swz(int row, int c) {
    return (uint32_t)(row * 64 + ((c ^ ((row >> 1) & 3)) << 4));
}

__device__ __forceinline__ void gemm_core(const __nv_bfloat16* __restrict__ Ah,
                                          const __nv_bfloat16* __restrict__ Al,
                                          const __nv_bfloat16* __restrict__ Bh,
                                          const __nv_bfloat16* __restrict__ Bl,
                                          const float* __restrict__ bias,
                                          __nv_bfloat16* __restrict__ Chi,
                                          __nv_bfloat16* __restrict__ Clo,
                                          float* __restrict__ Cf,
                                          char* sm, int bm, int bn)
{
    const uint32_t smb = (smem_to_u32(sm) + 127u) & ~127u;
    const int tid  = threadIdx.x;
    const int lane = tid & 31;
    const int wid  = tid >> 5;
    const int warp_m = wid >> 2;
    const int warp_n = wid & 3;

    float acc[4][4][4];
#pragma unroll
    for (int mi = 0; mi < 4; ++mi)
#pragma unroll
        for (int nj = 0; nj < 4; ++nj)
#pragma unroll
            for (int e = 0; e < 4; ++e) acc[mi][nj][e] = 0.f;

    auto issue = [&](int c, int j) {
        const int koff = c * 32;
        const uint32_t sb = smb + (uint32_t)j * STAGE_B;
#pragma unroll
        for (int u = tid; u < 512; u += 256) {
            const int row = u >> 2, cc = u & 3;
            const uint32_t so = swz(row, cc);
            const size_t gA = (size_t)(bm + row) * D_MODEL + koff + cc * 8;
            const size_t gB = (size_t)(bn + row) * D_MODEL + koff + cc * 8;
            CP_ASYNC16(sb + OFF_AH + so, Ah + gA);
            CP_ASYNC16(sb + OFF_AL + so, Al + gA);
            CP_ASYNC16(sb + OFF_BH + so, Bh + gB);
            CP_ASYNC16(sb + OFF_BL + so, Bl + gB);
        }
        CP_COMMIT();
    };

    const int rA = lane & 15, cA = lane >> 4;
    const uint32_t aoff = swz(rA, cA);
    const int rB = (lane & 7) | ((lane >> 4) << 3), cB = (lane >> 3) & 1;
    const uint32_t boff = swz(rB, cB);

    const uint32_t aH_base = smb + OFF_AH + (uint32_t)(warp_m * 4096) + aoff;
    const uint32_t aL_base = smb + OFF_AL + (uint32_t)(warp_m * 4096) + aoff;
    const uint32_t bH_base = smb + OFF_BH + (uint32_t)(warp_n * 2048) + boff;
    const uint32_t bL_base = smb + OFF_BL + (uint32_t)(warp_n * 2048) + boff;

    const int NCHUNK = D_MODEL / 32;
    issue(0, 0);
    issue(1, 1);

    for (int c = 0; c < NCHUNK; ++c) {
        const int j = c % NSTAGE;
        if (c + 1 < NCHUNK) { CP_WAIT1(); } else { CP_WAIT0(); }
        __syncthreads();
        if (c + 2 < NCHUNK) issue(c + 2, (c + 2) % NSTAGE);

        const uint32_t stg = (uint32_t)j * STAGE_B;
#pragma unroll
        for (int ks = 0; ks < 2; ++ks) {
            const uint32_t kx = (uint32_t)(ks << 5);
            uint32_t ah[4][4], al[4][4], bhv[4][2], blv[4][2];
#pragma unroll
            for (int mi = 0; mi < 4; ++mi) {
                ldm_x4(ah[mi], (aH_base + stg + (uint32_t)(mi * 1024)) ^ kx);
                ldm_x4(al[mi], (aL_base + stg + (uint32_t)(mi * 1024)) ^ kx);
            }
#pragma unroll
            for (int p = 0; p < 2; ++p) {
                uint32_t r[4];
                ldm_x4(r, (bH_base + stg + (uint32_t)(p * 1024)) ^ kx);
                bhv[p * 2 + 0][0] = r[0]; bhv[p * 2 + 0][1] = r[1];
                bhv[p * 2 + 1][0] = r[2]; bhv[p * 2 + 1][1] = r[3];
                ldm_x4(r, (bL_base + stg + (uint32_t)(p * 1024)) ^ kx);
                blv[p * 2 + 0][0] = r[0]; blv[p * 2 + 0][1] = r[1];
                blv[p * 2 + 1][0] = r[2]; blv[p * 2 + 1][1] = r[3];
            }
#pragma unroll
            for (int mi = 0; mi < 4; ++mi)
#pragma unroll
                for (int nj = 0; nj < 4; ++nj)
                    mma_bf16(acc[mi][nj], ah[mi], bhv[nj][0], bhv[nj][1]);
#pragma unroll
            for (int mi = 0; mi < 4; ++mi)
#pragma unroll
                for (int nj = 0; nj < 4; ++nj)
                    mma_bf16(acc[mi][nj], ah[mi], blv[nj][0], blv[nj][1]);
#pragma unroll
            for (int mi = 0; mi < 4; ++mi)
#pragma unroll
                for (int nj = 0; nj < 4; ++nj)
                    mma_bf16(acc[mi][nj], al[mi], bhv[nj][0], bhv[nj][1]);
        }
    }

    const int rbase = bm + warp_m * 64;
    const int cbase = bn + warp_n * 32;
#pragma unroll
    for (int mi = 0; mi < 4; ++mi) {
#pragma unroll
        for (int nj = 0; nj < 4; ++nj) {
            const int r0 = rbase + mi * 16 + (lane >> 2);
            const int cc = cbase + nj * 8 + 2 * (lane & 3);
            const float b0 = bias[cc], b1 = bias[cc + 1];
            const float v0 = acc[mi][nj][0] + b0, v1 = acc[mi][nj][1] + b1;
            const float v2 = acc[mi][nj][2] + b0, v3 = acc[mi][nj][3] + b1;
            if (Cf) {
                float2 w0, w1;
                w0.x = v0; w0.y = v1; w1.x = v2; w1.y = v3;
                *reinterpret_cast<float2*>(Cf + (size_t)r0 * D_MODEL + cc) = w0;
                *reinterpret_cast<float2*>(Cf + (size_t)(r0 + 8) * D_MODEL + cc) = w1;
            } else {
                uint32_t hp0 = cvt2bf(v1, v0);
                uint32_t hp1 = cvt2bf(v3, v2);
                float h0 = __uint_as_float(hp0 << 16), h1 = __uint_as_float(hp0 & 0xFFFF0000u);
                float h2 = __uint_as_float(hp1 << 16), h3 = __uint_as_float(hp1 & 0xFFFF0000u);
                uint32_t lp0 = cvt2bf(v1 - h1, v0 - h0);
                uint32_t lp1 = cvt2bf(v3 - h3, v2 - h2);
                *reinterpret_cast<uint32_t*>(Chi + (size_t)r0 * D_MODEL + cc) = hp0;
                *reinterpret_cast<uint32_t*>(Chi + (size_t)(r0 + 8) * D_MODEL + cc) = hp1;
                *reinterpret_cast<uint32_t*>(Clo + (size_t)r0 * D_MODEL + cc) = lp0;
                *reinterpret_cast<uint32_t*>(Clo + (size_t)(r0 + 8) * D_MODEL + cc) = lp1;
            }
        }
    }
}

__global__ __launch_bounds__(256, 2)
void gemm_qkv_kernel(const __nv_bfloat16* __restrict__ Ah3, const __nv_bfloat16* __restrict__ Al3,
                     const __nv_bfloat16* __restrict__ Wh4, const __nv_bfloat16* __restrict__ Wl4,
                     const float* __restrict__ bq, const float* __restrict__ bk,
                     const float* __restrict__ bv,
                     __nv_bfloat16* __restrict__ Qh, __nv_bfloat16* __restrict__ Ql,
                     __nv_bfloat16* __restrict__ Kh, __nv_bfloat16* __restrict__ Kl,
                     __nv_bfloat16* __restrict__ Vh, __nv_bfloat16* __restrict__ Vl)
{
    extern __shared__ char sm[];
    const int z = blockIdx.z;
    const float* bias = (z == 0) ? bq : (z == 1) ? bk : bv;
    __nv_bfloat16* Chi = (z == 0) ? Qh : (z == 1) ? Kh : Vh;
    __nv_bfloat16* Clo = (z == 0) ? Ql : (z == 1) ? Kl : Vl;
    gemm_core(Ah3 + (size_t)z * ASZ, Al3 + (size_t)z * ASZ,
              Wh4 + (size_t)z * WSZ, Wl4 + (size_t)z * WSZ,
              bias, Chi, Clo, nullptr, sm, blockIdx.y * 128, blockIdx.x * 128);
}

__global__ __launch_bounds__(256, 2)
void gemm_out_kernel(const __nv_bfloat16* __restrict__ Ah, const __nv_bfloat16* __restrict__ Al,
                     const __nv_bfloat16* __restrict__ Bh, const __nv_bfloat16* __restrict__ Bl,
                     const float* __restrict__ bias, float* __restrict__ Cf)
{
    extern __shared__ char sm[];
    gemm_core(Ah, Al, Bh, Bl, bias, nullptr, nullptr, Cf,
              sm, blockIdx.y * 128, blockIdx.x * 128);
}

// =====================================================================
// mma.sync flash attention — 9-bin LPT partition ({15},{14},{13,0}..{7,6}),
// max-free softmax, term-grouped MMA order, whole-tile causal warp skips.
// =====================================================================
#define QTERM_B  18432               // 128*72*2
#define KVARR_B  9216                // 64*72*2
#define STG_B    (4 * KVARR_B + 256)
#define FL_SMEM  (2 * QTERM_B + 2 * STG_B)   // 111104
#define SCL2E    0.180336879f        // 0.125 * log2(e)
#define NQB      (T_ / 128)          // 16

__global__ __launch_bounds__(256, 2)
void flash_tc_kernel(const __nv_bfloat16* __restrict__ Qh_g, const __nv_bfloat16* __restrict__ Ql_g,
                     const __nv_bfloat16* __restrict__ Kh_g, const __nv_bfloat16* __restrict__ Kl_g,
                     const __nv_bfloat16* __restrict__ Vh_g, const __nv_bfloat16* __restrict__ Vl_g,
                     const int* __restrict__ mask, const int* __restrict__ causal_p,
                     __nv_bfloat16* __restrict__ Oh_g, __nv_bfloat16* __restrict__ Ol_g)
{
    extern __shared__ char smc[];
    const uint32_t smb = smem_to_u32(smc);
    const int tid = threadIdx.x, lane = tid & 31, warp = tid >> 5;
    const int bin = blockIdx.x;                  // 0..8
    const int bh = blockIdx.y, b = bh >> 4, h = bh & 15;
    const int causal = *causal_p;

    // LPT bins: {15}=32, {14}=30, {13,0},{12,1},...,{7,6}=30 each
    int nblk, qbs[2];
    if (bin == 0)      { nblk = 1; qbs[0] = 15; qbs[1] = 0; }
    else if (bin == 1) { nblk = 1; qbs[0] = 14; qbs[1] = 0; }
    else               { nblk = 2; qbs[0] = 15 - bin; qbs[1] = bin - 2; }

    auto issue_kv = [&](int kt, int s) {
        const uint32_t sb = smb + 2u * QTERM_B + (uint32_t)s * STG_B;
        const int tk0 = b * T_ + kt * 64;
#pragma unroll
        for (int u = tid; u < 2048; u += 256) {
            const int arr = u >> 9, rem = u & 511;
            const int row = rem >> 3, c = rem & 7;
            const __nv_bfloat16* base = (arr == 0) ? Kh_g : (arr == 1) ? Kl_g
                                       : (arr == 2) ? Vh_g : Vl_g;
            CP_ASYNC16(sb + (uint32_t)(arr * KVARR_B + row * 144 + c * 16),
                       base + ((size_t)(tk0 + row) * D_MODEL + h * 64 + c * 8));
        }
        if (tid < 64) {
            float mv = (mask[tk0 + tid] == 0) ? -1e30f : 0.f;
            reinterpret_cast<float*>(smc + 2 * QTERM_B + s * STG_B + 4 * KVARR_B)[tid] = mv;
        }
    };

    const uint32_t a_lane = (uint32_t)((lane & 15) * 144 + (lane >> 4) * 16);
    const uint32_t b_lane = (uint32_t)(((lane & 7) + ((lane >> 4) << 3)) * 144 + ((lane >> 3) & 1) * 16);
    const uint32_t qsH = smb + (uint32_t)(warp * 16 * 144) + a_lane;
    const uint32_t qsL = qsH + QTERM_B;
    const int r_in_warp = lane >> 2;
    const int colb = 2 * (lane & 3);

    for (int blk = 0; blk < nblk; ++blk) {
        const int qb = qbs[blk];
        const int kend = causal ? (2 * qb + 1) : (T_ / 64 - 1);
        const int rowg0 = b * T_ + qb * 128;
        const int maxrow = qb * 128 + warp * 16 + 15;   // last q row this warp owns

        __syncthreads();   // all reads of previous block's Q smem are done

        {
#pragma unroll
            for (int u = tid; u < 2048; u += 256) {
                const int term = u >> 10, rem = u & 1023;
                const int row = rem >> 3, c = rem & 7;
                const __nv_bfloat16* src = (term ? Ql_g : Qh_g)
                    + ((size_t)(rowg0 + row) * D_MODEL + h * 64 + c * 8);
                CP_ASYNC16(smb + (uint32_t)(term * QTERM_B + row * 144 + c * 16), src);
            }
            issue_kv(0, 0);
            CP_COMMIT();
        }

        uint32_t qhf[4][4];
        float o[8][4];
#pragma unroll
        for (int nd = 0; nd < 8; ++nd)
#pragma unroll
            for (int e = 0; e < 4; ++e) o[nd][e] = 0.f;
        float l0 = 0.f, l1 = 0.f;

        const int rg0 = qb * 128 + warp * 16 + r_in_warp;
        const int rg1 = rg0 + 8;

        for (int kt = 0; kt <= kend; ++kt) {
            CP_WAIT0();
            __syncthreads();
            if (kt + 1 <= kend) { issue_kv(kt + 1, (kt + 1) & 1); CP_COMMIT(); }

            if (kt == 0) {
#pragma unroll
                for (int ks = 0; ks < 4; ++ks)
                    ldm_x4(qhf[ks], qsH + (uint32_t)(ks * 32));
            }

            const int j = kt & 1;
            const uint32_t sb = smb + 2u * QTERM_B + (uint32_t)j * STG_B;
            const float* madd = reinterpret_cast<const float*>(smc + 2 * QTERM_B + j * STG_B + 4 * KVARR_B);

            const bool diag = (causal != 0) && (kt >= 2 * qb);
            // whole tile above this warp's diagonal rows -> all-zero P; skip compute
            if (diag && kt * 64 > maxrow) continue;

            // ---- S = Q K^T (3-term), term-grouped across nb pairs ----
            float c[8][4];
#pragma unroll
            for (int nj = 0; nj < 8; ++nj)
#pragma unroll
                for (int e = 0; e < 4; ++e) c[nj][e] = 0.f;

#pragma unroll
            for (int ks = 0; ks < 4; ++ks) {
                const uint32_t kb = (uint32_t)(ks * 32);
                uint32_t qlf[4];
                ldm_x4(qlf, qsL + kb);
#pragma unroll
                for (int np = 0; np < 2; ++np) {
                    uint32_t rh[2][4], rl[2][4];
                    const uint32_t kb0 = sb + b_lane + (uint32_t)((2 * np) * 2304) + kb;
                    ldm_x4(rh[0], kb0);
                    ldm_x4(rl[0], kb0 + KVARR_B);
                    ldm_x4(rh[1], kb0 + 2304u);
                    ldm_x4(rl[1], kb0 + 2304u + KVARR_B);
                    float* c0 = c[4 * np + 0];
                    float* c1 = c[4 * np + 1];
                    float* c2 = c[4 * np + 2];
                    float* c3 = c[4 * np + 3];
                    // term 1: Qh x Kh
                    mma_bf16(c0, qhf[ks], rh[0][0], rh[0][1]);
                    mma_bf16(c1, qhf[ks], rh[0][2], rh[0][3]);
                    mma_bf16(c2, qhf[ks], rh[1][0], rh[1][1]);
                    mma_bf16(c3, qhf[ks], rh[1][2], rh[1][3]);
                    // term 2: Qh x Kl
                    mma_bf16(c0, qhf[ks], rl[0][0], rl[0][1]);
                    mma_bf16(c1, qhf[ks], rl[0][2], rl[0][3]);
                    mma_bf16(c2, qhf[ks], rl[1][0], rl[1][1]);
                    mma_bf16(c3, qhf[ks], rl[1][2], rl[1][3]);
                    // term 3: Ql x Kh
                    mma_bf16(c0, qlf, rh[0][0], rh[0][1]);
                    mma_bf16(c1, qlf, rh[0][2], rh[0][3]);
                    mma_bf16(c2, qlf, rh[1][0], rh[1][1]);
                    mma_bf16(c3, qlf, rh[1][2], rh[1][3]);
                }
            }

            // ---- max-free softmax: p = exp2(c*scale + mask), accumulate sum ----
            float rs0 = 0.f, rs1 = 0.f;
#pragma unroll
            for (int nj = 0; nj < 8; ++nj) {
                const int cl = nj * 8 + colb;
                const int cg = kt * 64 + cl;
                const float ma0 = madd[cl], ma1 = madd[cl + 1];
                float s0 = fmaf(c[nj][0], SCL2E, ma0);
                float s1 = fmaf(c[nj][1], SCL2E, ma1);
                float s2 = fmaf(c[nj][2], SCL2E, ma0);
                float s3 = fmaf(c[nj][3], SCL2E, ma1);
                if (diag) {
                    if (cg > rg0)     s0 = -1e30f;
                    if (cg + 1 > rg0) s1 = -1e30f;
                    if (cg > rg1)     s2 = -1e30f;
                    if (cg + 1 > rg1) s3 = -1e30f;
                }
                float p0 = ex2f(s0);
                float p1 = ex2f(s1);
                float p2 = ex2f(s2);
                float p3 = ex2f(s3);
                c[nj][0] = p0; c[nj][1] = p1; c[nj][2] = p2; c[nj][3] = p3;
                rs0 += p0 + p1; rs1 += p2 + p3;
            }
            l0 += rs0;
            l1 += rs1;

            // ---- O += P V (3-term), term-grouped across nb pairs ----
#pragma unroll
            for (int ks = 0; ks < 4; ++ks) {
                uint32_t pfh[4], pfl[4];
#pragma unroll
                for (int half = 0; half < 2; ++half) {
                    const int nj = 2 * ks + half;
                    uint32_t hpA = cvt2bf(c[nj][1], c[nj][0]);
                    uint32_t hpB = cvt2bf(c[nj][3], c[nj][2]);
                    float hA0 = __uint_as_float(hpA << 16), hA1 = __uint_as_float(hpA & 0xFFFF0000u);
                    float hB0 = __uint_as_float(hpB << 16), hB1 = __uint_as_float(hpB & 0xFFFF0000u);
                    pfh[2 * half + 0] = hpA; pfh[2 * half + 1] = hpB;
                    pfl[2 * half + 0] = cvt2bf(c[nj][1] - hA1, c[nj][0] - hA0);
                    pfl[2 * half + 1] = cvt2bf(c[nj][3] - hB1, c[nj][2] - hB0);
                }
#pragma unroll
                for (int np = 0; np < 2; ++np) {
                    uint32_t vh[2][4], vl[2][4];
                    const uint32_t va = sb + 2u * KVARR_B + a_lane
                                      + (uint32_t)(ks * 16 * 144) + (uint32_t)((2 * np) * 32);
                    ldm_x4_t(vh[0], va);
                    ldm_x4_t(vl[0], va + KVARR_B);
                    ldm_x4_t(vh[1], va + 32u);
                    ldm_x4_t(vl[1], va + 32u + KVARR_B);
                    float* o0 = o[4 * np + 0];
                    float* o1 = o[4 * np + 1];
                    float* o2 = o[4 * np + 2];
                    float* o3 = o[4 * np + 3];
                    // term 1: Ph x Vh
                    mma_bf16(o0, pfh, vh[0][0], vh[0][1]);
                    mma_bf16(o1, pfh, vh[0][2], vh[0][3]);
                    mma_bf16(o2, pfh, vh[1][0], vh[1][1]);
                    mma_bf16(o3, pfh, vh[1][2], vh[1][3]);
                    // term 2: Ph x Vl
                    mma_bf16(o0, pfh, vl[0][0], vl[0][1]);
                    mma_bf16(o1, pfh, vl[0][2], vl[0][3]);
                    mma_bf16(o2, pfh, vl[1][0], vl[1][1]);
                    mma_bf16(o3, pfh, vl[1][2], vl[1][3]);
                    // term 3: Pl x Vh
                    mma_bf16(o0, pfl, vh[0][0], vh[0][1]);
                    mma_bf16(o1, pfl, vh[0][2], vh[0][3]);
                    mma_bf16(o2, pfl, vh[1][0], vh[1][1]);
                    mma_bf16(o3, pfl, vh[1][2], vh[1][3]);
                }
            }
        }

        // ---- epilogue: reduce row sums across quad lanes, normalize ----
        l0 += __shfl_xor_sync(0xffffffffu, l0, 1);
        l0 += __shfl_xor_sync(0xffffffffu, l0, 2);
        l1 += __shfl_xor_sync(0xffffffffu, l1, 1);
        l1 += __shfl_xor_sync(0xffffffffu, l1, 2);
        const float inv0 = __fdividef(1.f, l0);
        const float inv1 = __fdividef(1.f, l1);
        const size_t gr0 = (size_t)(rowg0 + warp * 16 + r_in_warp) * D_MODEL + h * 64;
        const size_t gr1 = gr0 + 8 * D_MODEL;
#pragma unroll
        for (int nd = 0; nd < 8; ++nd) {
            const int cc = nd * 8 + colb;
            float v0 = o[nd][0] * inv0, v1 = o[nd][1] * inv0;
            float v2 = o[nd][2] * inv1, v3 = o[nd][3] * inv1;
            uint32_t hp0 = cvt2bf(v1, v0);
            uint32_t hp1 = cvt2bf(v3, v2);
            float h0 = __uint_as_float(hp0 << 16), h1 = __uint_as_float(hp0 & 0xFFFF0000u);
            float h2 = __uint_as_float(hp1 << 16), h3 = __uint_as_float(hp1 & 0xFFFF0000u);
            uint32_t lp0 = cvt2bf(v1 - h1, v0 - h0);
            uint32_t lp1 = cvt2bf(v3 - h3, v2 - h2);
            *reinterpret_cast<uint32_t*>(Oh_g + gr0 + cc) = hp0;
            *reinterpret_cast<uint32_t*>(Oh_g + gr1 + cc) = hp1;
            *reinterpret_cast<uint32_t*>(Ol_g + gr0 + cc) = lp0;
            *reinterpret_cast<uint32_t*>(Ol_g + gr1 + cc) = lp1;
        }
    }
}

// =====================================================================
// launch
// =====================================================================
extern "C" void kernel_launch(void* const* d_in, const int* in_sizes, int n_in,
                              void* d_out, int out_size)
{
    const float* q    = (const float*)d_in[0];
    const float* k    = (const float*)d_in[1];
    const float* v    = (const float*)d_in[2];
    const float* Wq   = (const float*)d_in[3];
    const float* bq   = (const float*)d_in[4];
    const float* Wk   = (const float*)d_in[5];
    const float* bk   = (const float*)d_in[6];
    const float* Wv   = (const float*)d_in[7];
    const float* bv   = (const float*)d_in[8];
    const float* Wo   = (const float*)d_in[9];
    const float* bo   = (const float*)d_in[10];
    const int*   mask = (const int*)d_in[11];
    const int*   causal = (const int*)d_in[12];
    float* out = (float*)d_out;

    __nv_bfloat16 *Ah, *Al, *Wh, *Wl, *Qh, *Ql, *Kh, *Kl, *Vh, *Vl, *Anh, *Anl;
    cudaGetSymbolAddress((void**)&Ah, g_Ah);
    cudaGetSymbolAddress((void**)&Al, g_Al);
    cudaGetSymbolAddress((void**)&Wh, g_Wh);
    cudaGetSymbolAddress((void**)&Wl, g_Wl);
    cudaGetSymbolAddress((void**)&Qh, g_Qh);
    cudaGetSymbolAddress((void**)&Ql, g_Ql);
    cudaGetSymbolAddress((void**)&Kh, g_Kh);
    cudaGetSymbolAddress((void**)&Kl, g_Kl);
    cudaGetSymbolAddress((void**)&Vh, g_Vh);
    cudaGetSymbolAddress((void**)&Vl, g_Vl);
    cudaGetSymbolAddress((void**)&Anh, g_Anh);
    cudaGetSymbolAddress((void**)&Anl, g_Anl);

    cudaFuncSetAttribute(gemm_qkv_kernel,
                         cudaFuncAttributeMaxDynamicSharedMemorySize, GEMM_SMEM);
    cudaFuncSetAttribute(gemm_out_kernel,
                         cudaFuncAttributeMaxDynamicSharedMemorySize, GEMM_SMEM);
    cudaFuncSetAttribute(flash_tc_kernel,
                         cudaFuncAttributeMaxDynamicSharedMemorySize, FL_SMEM);

    const int nA4 = ASZ / 4;
    const int nW4 = WSZ / 4;

    split3_kernel<<<dim3(nA4 / 256, 1, 3), 256>>>(q, k, v, Ah, Al);
    split4_kernel<<<dim3(nW4 / 256, 1, 4), 256>>>(Wq, Wk, Wv, Wo, Wh, Wl);

    gemm_qkv_kernel<<<dim3(D_MODEL / 128, M_ROWS / 128, 3), 256, GEMM_SMEM>>>(
        Ah, Al, Wh, Wl, bq, bk, bv, Qh, Ql, Kh, Kl, Vh, Vl);

    dim3 fgrid(9, B_ * N_HEADS);   // 288 CTAs: 9 LPT bins x 32 (b,h), one wave
    flash_tc_kernel<<<fgrid, 256, FL_SMEM>>>(Qh, Ql, Kh, Kl, Vh, Vl, mask, causal, Anh, Anl);

    gemm_out_kernel<<<dim3(D_MODEL / 128, M_ROWS / 128), 256, GEMM_SMEM>>>(
        Anh, Anl, Wh + (size_t)3 * WSZ, Wl + (size_t)3 * WSZ, bo, out);
}